// round 12
// baseline (speedup 1.0000x reference)
#include <cuda_runtime.h>

#define Bsz 2048
#define Ncm 128
#define Dh  512

// 8MB scratch for cw = content @ cow  (rows interleaved: m = 2*b + k)
__device__ float g_cw[2 * Bsz * Dh];

__device__ __forceinline__ float fast_tanh(float x) {
    float y;
    asm("tanh.approx.f32 %0, %1;" : "=f"(y) : "f"(x));
    return y;
}

__device__ __forceinline__ unsigned int to_tf32(float v) {
    unsigned int r;
    asm("cvt.rna.tf32.f32 %0, %1;" : "=r"(r) : "f"(v));
    return r;
}

__device__ __forceinline__ void mma_tf32(float& c0, float& c1, float& c2, float& c3,
                                         unsigned int a0, unsigned int a1,
                                         unsigned int a2, unsigned int a3,
                                         unsigned int b0, unsigned int b1) {
    asm("mma.sync.aligned.m16n8k8.row.col.f32.tf32.tf32.f32 "
        "{%0,%1,%2,%3}, {%4,%5,%6,%7}, {%8,%9}, {%0,%1,%2,%3};"
        : "+f"(c0), "+f"(c1), "+f"(c2), "+f"(c3)
        : "r"(a0), "r"(a1), "r"(a2), "r"(a3), "r"(b0), "r"(b1));
}

// ---------------------------------------------------------------------------
// Kernel 1: cw[m, e] = sum_d A[m, d] * cow[d, e]   — tf32 tensor-core GEMM
// with 3xTF32 split (aH*bH + aH*bL + aL*bH) for ~fp32 accuracy.
// ---------------------------------------------------------------------------
#define TM 128
#define TN 128
#define TK 16
#define APITCH (TK + 4)
#define BPITCH (TN + 8)

__global__ __launch_bounds__(256) void gemm_cw_kernel(
    const float* __restrict__ text,
    const float* __restrict__ img,
    const float* __restrict__ cow)
{
    __shared__ unsigned int AsH[TM * APITCH];
    __shared__ unsigned int AsL[TM * APITCH];
    __shared__ unsigned int BsH[TK * BPITCH];
    __shared__ unsigned int BsL[TK * BPITCH];

    const int tid = threadIdx.x;
    const int m0g = blockIdx.y * TM;
    const int n0g = blockIdx.x * TN;

    const int warp = tid >> 5;
    const int lane = tid & 31;
    const int wm = warp & 1;
    const int wn = warp >> 1;
    const int g  = lane >> 2;
    const int t  = lane & 3;

    const int ar = tid >> 1;
    const int ah = tid & 1;
    const int am = m0g + ar;
    const float* asrc = ((am & 1) ? img : text) + (size_t)(am >> 1) * Dh + ah * 8;
    const int bk = tid >> 4;
    const int bc = tid & 15;
    const float* bsrc = cow + (size_t)bk * Dh + n0g + bc * 8;

    float acc[4][4][4];
#pragma unroll
    for (int f = 0; f < 4; f++)
#pragma unroll
        for (int j = 0; j < 4; j++)
#pragma unroll
            for (int c = 0; c < 4; c++) acc[f][j][c] = 0.0f;

    float4 aR0 = *(const float4*)(asrc);
    float4 aR1 = *(const float4*)(asrc + 4);
    float4 bR0 = *(const float4*)(bsrc);
    float4 bR1 = *(const float4*)(bsrc + 4);

    for (int kk = 0; kk < Dh; kk += TK) {
        {
            float av[8] = {aR0.x, aR0.y, aR0.z, aR0.w, aR1.x, aR1.y, aR1.z, aR1.w};
            unsigned int hi[8], lo[8];
#pragma unroll
            for (int i = 0; i < 8; i++) {
                hi[i] = to_tf32(av[i]);
                lo[i] = to_tf32(av[i] - __uint_as_float(hi[i]));
            }
            unsigned int* pH = &AsH[ar * APITCH + ah * 8];
            unsigned int* pL = &AsL[ar * APITCH + ah * 8];
            *(uint4*)pH       = make_uint4(hi[0], hi[1], hi[2], hi[3]);
            *(uint4*)(pH + 4) = make_uint4(hi[4], hi[5], hi[6], hi[7]);
            *(uint4*)pL       = make_uint4(lo[0], lo[1], lo[2], lo[3]);
            *(uint4*)(pL + 4) = make_uint4(lo[4], lo[5], lo[6], lo[7]);

            float bv[8] = {bR0.x, bR0.y, bR0.z, bR0.w, bR1.x, bR1.y, bR1.z, bR1.w};
#pragma unroll
            for (int i = 0; i < 8; i++) {
                hi[i] = to_tf32(bv[i]);
                lo[i] = to_tf32(bv[i] - __uint_as_float(hi[i]));
            }
            unsigned int* qH = &BsH[bk * BPITCH + bc * 8];
            unsigned int* qL = &BsL[bk * BPITCH + bc * 8];
            *(uint4*)qH       = make_uint4(hi[0], hi[1], hi[2], hi[3]);
            *(uint4*)(qH + 4) = make_uint4(hi[4], hi[5], hi[6], hi[7]);
            *(uint4*)qL       = make_uint4(lo[0], lo[1], lo[2], lo[3]);
            *(uint4*)(qL + 4) = make_uint4(lo[4], lo[5], lo[6], lo[7]);
        }
        __syncthreads();

        if (kk + TK < Dh) {
            aR0 = *(const float4*)(asrc + kk + TK);
            aR1 = *(const float4*)(asrc + kk + TK + 4);
            const float* bnext = cow + (size_t)(kk + TK + bk) * Dh + n0g + bc * 8;
            bR0 = *(const float4*)(bnext);
            bR1 = *(const float4*)(bnext + 4);
        }

#pragma unroll
        for (int ks = 0; ks < 2; ks++) {
            const int k0 = ks * 8;
            unsigned int aH[4][4], aL[4][4];
#pragma unroll
            for (int f = 0; f < 4; f++) {
                int r0 = (wm * 64 + f * 16 + g) * APITCH + k0 + t;
                int r1 = r0 + 8 * APITCH;
                aH[f][0] = AsH[r0];     aH[f][1] = AsH[r1];
                aH[f][2] = AsH[r0 + 4]; aH[f][3] = AsH[r1 + 4];
                aL[f][0] = AsL[r0];     aL[f][1] = AsL[r1];
                aL[f][2] = AsL[r0 + 4]; aL[f][3] = AsL[r1 + 4];
            }
            unsigned int bH[4][2], bL[4][2];
#pragma unroll
            for (int j = 0; j < 4; j++) {
                int c0i = (k0 + t) * BPITCH + wn * 32 + j * 8 + g;
                int c1i = c0i + 4 * BPITCH;
                bH[j][0] = BsH[c0i]; bH[j][1] = BsH[c1i];
                bL[j][0] = BsL[c0i]; bL[j][1] = BsL[c1i];
            }
#pragma unroll
            for (int f = 0; f < 4; f++)
#pragma unroll
                for (int j = 0; j < 4; j++) {
                    mma_tf32(acc[f][j][0], acc[f][j][1], acc[f][j][2], acc[f][j][3],
                             aH[f][0], aH[f][1], aH[f][2], aH[f][3], bH[j][0], bH[j][1]);
                    mma_tf32(acc[f][j][0], acc[f][j][1], acc[f][j][2], acc[f][j][3],
                             aH[f][0], aH[f][1], aH[f][2], aH[f][3], bL[j][0], bL[j][1]);
                    mma_tf32(acc[f][j][0], acc[f][j][1], acc[f][j][2], acc[f][j][3],
                             aL[f][0], aL[f][1], aL[f][2], aL[f][3], bH[j][0], bH[j][1]);
                }
        }
        __syncthreads();
    }

#pragma unroll
    for (int f = 0; f < 4; f++) {
        int row0 = m0g + wm * 64 + f * 16 + g;
#pragma unroll
        for (int j = 0; j < 4; j++) {
            int col = n0g + wn * 32 + j * 8 + 2 * t;
            *(float2*)&g_cw[(size_t)row0 * Dh + col] =
                make_float2(acc[f][j][0], acc[f][j][1]);
            *(float2*)&g_cw[(size_t)(row0 + 8) * Dh + col] =
                make_float2(acc[f][j][2], acc[f][j][3]);
        }
    }
}

// ---------------------------------------------------------------------------
// Kernel 2: fused co-attention — tiled multi-phase. One CTA/sample, 4 warps,
// 4 CTAs/SM. Each warp handles 4 rows per 16-row tile in phases:
//   A : per-lane dot partials for 4 rows (z streamed from gmem chunk-wise),
//       then ONE batched 8-chain butterfly reduction + tanh -> co0/co1 (regs)
//   B1: logits + caA/caB accumulation, z re-read from L1, batched pd reduce
//   B2: accv += e*z, z from L1
// Large operands (w0,w1,c0,c1,wco) live in smem; z never held whole in regs.
// ---------------------------------------------------------------------------
__global__ __launch_bounds__(128, 4) void fused_coattn_kernel(
    const float* __restrict__ text,
    const float* __restrict__ img,
    const float* __restrict__ comment,
    const int*   __restrict__ comment_num,
    const float* __restrict__ W_ca,
    const float* __restrict__ b_ca,
    const float* __restrict__ W_co,
    const float* __restrict__ b_co,
    float* __restrict__ out)
{
    const int b    = blockIdx.x;
    const int tid  = threadIdx.x;
    const int lane = tid & 31;
    const int warp = tid >> 5;
    const int loff = lane * 4;

    __shared__ float sw0[Dh], sw1[Dh], sc0[Dh], sc1[Dh], swco[Dh];  // 10 KB
    __shared__ float sbuf[4 * Dh];                                   // 8 KB
    __shared__ float rA[Dh], rB[Dh], rC[Dh];                         // 6 KB
    __shared__ float swr[4];
    __shared__ float pr[8];
    __shared__ float sscal[3];

    int cn = comment_num[b];
    if (cn > Ncm) cn = Ncm;
    if (cn < 1)   cn = 1;

    const float* tp  = text + (size_t)b * Dh;
    const float* ip  = img  + (size_t)b * Dh;
    const float* w0p = g_cw + (size_t)(2 * b) * Dh;
    const float* w1p = w0p + Dh;

    // cooperative smem fill: 128 threads x float4 = 512 floats per array
    {
        int d = tid * 4;
        *(float4*)&sw0[d]  = *(const float4*)(w0p + d);
        *(float4*)&sw1[d]  = *(const float4*)(w1p + d);
        *(float4*)&sc0[d]  = *(const float4*)(tp + d);
        *(float4*)&sc1[d]  = *(const float4*)(ip + d);
        *(float4*)&swco[d] = *(const float4*)(W_co + d);
    }
    __syncthreads();

    float caA[16], caB[16], accv[16];
#pragma unroll
    for (int i = 0; i < 16; i++) { caA[i] = 0.f; caB[i] = 0.f; accv[i] = 0.f; }
    float ssum = 0.0f;
    const float bco = b_co[0];

    const float* cbase = comment + (size_t)b * Ncm * Dh + loff;
    const int ntiles = (cn + 15) >> 4;

    // warm L1: tiles 0 and 1 (this warp's rows)
#pragma unroll
    for (int tpre = 0; tpre < 2; tpre++) {
#pragma unroll
        for (int r = 0; r < 4; r++) {
            int row = tpre * 16 + warp * 4 + r;
            if (row < cn) {
                const float* p = cbase + (size_t)row * Dh;
#pragma unroll
                for (int q = 0; q < 4; q++)
                    asm volatile("prefetch.global.L1 [%0];" :: "l"(p + q * 128));
            }
        }
    }

    for (int tb = 0; tb < ntiles; tb++) {
        const int rbase = tb * 16 + warp * 4;
        int   rows[4];
        float msk[4];
#pragma unroll
        for (int r = 0; r < 4; r++) {
            int rr = rbase + r;
            msk[r]  = (rr < cn) ? 1.0f : 0.0f;
            rows[r] = (rr < cn) ? rr : 0;
        }

        // ---- Phase A: per-lane dot partials for 4 rows ----
        float d0p[4], d1p[4];
#pragma unroll
        for (int r = 0; r < 4; r++) {
            const float* zr = cbase + (size_t)rows[r] * Dh;
            float a0 = 0.f, a1 = 0.f;
#pragma unroll
            for (int q = 0; q < 4; q++) {
                float4 zv  = *(const float4*)(zr + q * 128);
                float4 w0v = *(const float4*)&sw0[q * 128 + loff];
                float4 w1v = *(const float4*)&sw1[q * 128 + loff];
                a0 += w0v.x * zv.x + w0v.y * zv.y + w0v.z * zv.z + w0v.w * zv.w;
                a1 += w1v.x * zv.x + w1v.y * zv.y + w1v.z * zv.z + w1v.w * zv.w;
            }
            d0p[r] = a0; d1p[r] = a1;
        }

        // prefetch tile tb+2 while reductions run
        {
            int pt = tb + 2;
            if (pt < ntiles) {
#pragma unroll
                for (int r = 0; r < 4; r++) {
                    int row = pt * 16 + warp * 4 + r;
                    if (row < cn) {
                        const float* p = cbase + (size_t)row * Dh;
#pragma unroll
                        for (int q = 0; q < 4; q++)
                            asm volatile("prefetch.global.L1 [%0];" :: "l"(p + q * 128));
                    }
                }
            }
        }

        // batched butterfly: 8 interleaved chains
#pragma unroll
        for (int o = 16; o > 0; o >>= 1) {
#pragma unroll
            for (int r = 0; r < 4; r++) {
                d0p[r] += __shfl_xor_sync(0xffffffffu, d0p[r], o);
                d1p[r] += __shfl_xor_sync(0xffffffffu, d1p[r], o);
            }
        }
        float co0[4], co1[4];
#pragma unroll
        for (int r = 0; r < 4; r++) {
            co0[r] = fast_tanh(d0p[r]) * msk[r];
            co1[r] = fast_tanh(d1p[r]) * msk[r];
        }

        // ---- Phase B1: logits + caA/caB (z from L1) ----
        float pdp[4];
#pragma unroll
        for (int r = 0; r < 4; r++) {
            const float* zr = cbase + (size_t)rows[r] * Dh;
            float pp = 0.f;
#pragma unroll
            for (int q = 0; q < 4; q++) {
                float4 zv  = *(const float4*)(zr + q * 128);
                float4 c0v = *(const float4*)&sc0[q * 128 + loff];
                float4 c1v = *(const float4*)&sc1[q * 128 + loff];
                float4 wv  = *(const float4*)&swco[q * 128 + loff];
                const float zj[4] = {zv.x, zv.y, zv.z, zv.w};
                const float aj[4] = {c0v.x, c0v.y, c0v.z, c0v.w};
                const float bj[4] = {c1v.x, c1v.y, c1v.z, c1v.w};
                const float wj[4] = {wv.x, wv.y, wv.z, wv.w};
#pragma unroll
                for (int j = 0; j < 4; j++) {
                    caA[q * 4 + j] += co0[r] * zj[j];
                    caB[q * 4 + j] += co1[r] * zj[j];
                    float t = fast_tanh(zj[j] + co0[r] * aj[j] + co1[r] * bj[j]);
                    pp += t * wj[j];
                }
            }
            pdp[r] = pp;
        }
#pragma unroll
        for (int o = 16; o > 0; o >>= 1) {
#pragma unroll
            for (int r = 0; r < 4; r++)
                pdp[r] += __shfl_xor_sync(0xffffffffu, pdp[r], o);
        }
        float ev[4];
#pragma unroll
        for (int r = 0; r < 4; r++) {
            // |logit| <= ||W_co||_1 ~ 18, raw exp safe in fp32.
            ev[r] = __expf(pdp[r] + bco) * msk[r];
            ssum += ev[r];
        }

        // ---- Phase B2: accv += e*z (z from L1) ----
#pragma unroll
        for (int r = 0; r < 4; r++) {
            const float* zr = cbase + (size_t)rows[r] * Dh;
#pragma unroll
            for (int q = 0; q < 4; q++) {
                float4 zv = *(const float4*)(zr + q * 128);
                accv[q * 4 + 0] += ev[r] * zv.x;
                accv[q * 4 + 1] += ev[r] * zv.y;
                accv[q * 4 + 2] += ev[r] * zv.z;
                accv[q * 4 + 3] += ev[r] * zv.w;
            }
        }
    }

    // ---- cross-warp reductions via smem ----
    if (lane == 0) swr[warp] = ssum;

#pragma unroll
    for (int q = 0; q < 4; q++)
        *(float4*)&sbuf[warp * Dh + q * 128 + loff] = ((float4*)caA)[q];
    __syncthreads();
    for (int d = tid; d < Dh; d += 128) {
        float s = 0.f;
#pragma unroll
        for (int w = 0; w < 4; w++) s += sbuf[w * Dh + d];
        rA[d] = s;
    }
    __syncthreads();
#pragma unroll
    for (int q = 0; q < 4; q++)
        *(float4*)&sbuf[warp * Dh + q * 128 + loff] = ((float4*)caB)[q];
    __syncthreads();
    for (int d = tid; d < Dh; d += 128) {
        float s = 0.f;
#pragma unroll
        for (int w = 0; w < 4; w++) s += sbuf[w * Dh + d];
        rB[d] = s;
    }
    __syncthreads();
#pragma unroll
    for (int q = 0; q < 4; q++)
        *(float4*)&sbuf[warp * Dh + q * 128 + loff] = ((float4*)accv)[q];
    __syncthreads();
    for (int d = tid; d < Dh; d += 128) {
        float s = 0.f;
#pragma unroll
        for (int w = 0; w < 4; w++) s += sbuf[w * Dh + d];
        rC[d] = s;
    }
    __syncthreads();

    // ---- content attention logits ----
    float p0 = 0.f, p1 = 0.f;
    for (int d = tid; d < Dh; d += 128) {
        float wa = W_ca[d];
        p0 += fast_tanh(sc0[d] + rA[d]) * wa;
        p1 += fast_tanh(sc1[d] + rB[d]) * wa;
    }
#pragma unroll
    for (int o = 16; o > 0; o >>= 1) {
        p0 += __shfl_xor_sync(0xffffffffu, p0, o);
        p1 += __shfl_xor_sync(0xffffffffu, p1, o);
    }
    if (lane == 0) { pr[warp] = p0; pr[4 + warp] = p1; }
    __syncthreads();

    if (tid == 0) {
        float bca = b_ca[0];
        float l0 = bca, l1 = bca;
#pragma unroll
        for (int w = 0; w < 4; w++) { l0 += pr[w]; l1 += pr[4 + w]; }
        float mx = fmaxf(l0, l1);
        float e0 = __expf(l0 - mx), e1 = __expf(l1 - mx);
        float inv = __fdividef(1.0f, e0 + e1);
        float st = 0.f;
#pragma unroll
        for (int w = 0; w < 4; w++) st += swr[w];
        sscal[0] = e0 * inv;
        sscal[1] = e1 * inv;
        sscal[2] = __fdividef(1.0f, st);
    }
    __syncthreads();

    const float cwt0 = sscal[0], cwt1 = sscal[1], invs = sscal[2];
    for (int d = tid; d < Dh; d += 128) {
        out[(size_t)b * Dh + d]         = sc0[d] * cwt0 + sc1[d] * cwt1;
        out[(size_t)(Bsz + b) * Dh + d] = rC[d] * invs;
    }
    if (tid == 0) {
        out[(size_t)2 * Bsz * Dh + 2 * b]     = cwt0;
        out[(size_t)2 * Bsz * Dh + 2 * b + 1] = cwt1;
    }
}

// ---------------------------------------------------------------------------
extern "C" void kernel_launch(void* const* d_in, const int* in_sizes, int n_in,
                              void* d_out, int out_size)
{
    const float* text    = (const float*)d_in[0];
    const float* img     = (const float*)d_in[1];
    const float* comment = (const float*)d_in[2];
    const int*   cnum    = (const int*)d_in[3];
    const float* cow     = (const float*)d_in[4];
    const float* W_ca    = (const float*)d_in[5];
    const float* b_ca    = (const float*)d_in[6];
    const float* W_co    = (const float*)d_in[7];
    const float* b_co    = (const float*)d_in[8];
    float* out = (float*)d_out;

    dim3 ggrid(Dh / TN, (2 * Bsz) / TM);   // (4, 32) = 128 CTAs
    gemm_cw_kernel<<<ggrid, 256>>>(text, img, cow);
    fused_coattn_kernel<<<Bsz, 128>>>(text, img, comment, cnum,
                                      W_ca, b_ca, W_co, b_co, out);
}

// round 14
// speedup vs baseline: 1.2401x; 1.2401x over previous
#include <cuda_runtime.h>
#include <cuda_bf16.h>

#define Bsz 2048
#define Ncm 128
#define Dh  512

// 8MB scratch for cw = content @ cow  (rows interleaved: m = 2*b + k)
__device__ float g_cw[2 * Bsz * Dh];
// cow transposed + bf16-split: [e][k-pair] packed as uint ({bf(k),bf(k+1)})
__device__ unsigned g_BThi[Dh * (Dh / 2)];
__device__ unsigned g_BTlo[Dh * (Dh / 2)];

__device__ __forceinline__ float fast_tanh(float x) {
    float y;
    asm("tanh.approx.f32 %0, %1;" : "=f"(y) : "f"(x));
    return y;
}

__device__ __forceinline__ void mma_bf16(float& c0, float& c1, float& c2, float& c3,
                                         unsigned a0, unsigned a1,
                                         unsigned a2, unsigned a3,
                                         unsigned b0, unsigned b1) {
    asm("mma.sync.aligned.m16n8k16.row.col.f32.bf16.bf16.f32 "
        "{%0,%1,%2,%3}, {%4,%5,%6,%7}, {%8,%9}, {%0,%1,%2,%3};"
        : "+f"(c0), "+f"(c1), "+f"(c2), "+f"(c3)
        : "r"(a0), "r"(a1), "r"(a2), "r"(a3), "r"(b0), "r"(b1));
}

// ---------------------------------------------------------------------------
// Kernel 0: transpose + bf16-split cow -> g_BThi/g_BTlo  ([e][k/2] uint pairs)
// ---------------------------------------------------------------------------
__global__ __launch_bounds__(256) void prep_bt_kernel(const float* __restrict__ cow)
{
    __shared__ float tile[32][33];
    const int e0 = blockIdx.x * 32;
    const int d0 = blockIdx.y * 32;
    const int tx = threadIdx.x & 31;
    const int ty = threadIdx.x >> 5;      // 0..7
#pragma unroll
    for (int i = 0; i < 4; i++)
        tile[ty + 8 * i][tx] = cow[(size_t)(d0 + ty + 8 * i) * Dh + e0 + tx];
    __syncthreads();

    const int p  = threadIdx.x & 15;      // d-pair 0..15
    const int er = threadIdx.x >> 4;      // 0..15
#pragma unroll
    for (int i = 0; i < 2; i++) {
        int e = er + 16 * i;
        float x0 = tile[2 * p][e];
        float x1 = tile[2 * p + 1][e];
        __nv_bfloat162 h2 = __floats2bfloat162_rn(x0, x1);
        float hx = __bfloat162float(h2.x);
        float hy = __bfloat162float(h2.y);
        __nv_bfloat162 l2 = __floats2bfloat162_rn(x0 - hx, x1 - hy);
        size_t idx = (size_t)(e0 + e) * (Dh / 2) + (d0 >> 1) + p;
        g_BThi[idx] = *(unsigned*)&h2;
        g_BTlo[idx] = *(unsigned*)&l2;
    }
}

// ---------------------------------------------------------------------------
// Kernel 1: cw[m, e] = sum_d A[m, d] * cow[d, e] — bf16 tensor-core GEMM with
// 3-term split (aH*bH + aH*bL + aL*bH).  M=4096, N=K=512.
// CTA tile 128x128, TK=32 (2 k16-steps), 256 threads = 8 warps (2M x 4N),
// warp tile 64x32 of m16n8k16 fragments.
// Smem pitch 20 uints/row -> fragment banks (20g+t)%32 all distinct.
// ---------------------------------------------------------------------------
#define TM 128
#define TN 128
#define TK 32
#define PIT 20   // uints per smem row (16 k-pairs + 4 pad)

__global__ __launch_bounds__(256) void gemm_cw_kernel(
    const float* __restrict__ text,
    const float* __restrict__ img)
{
    __shared__ unsigned AsH[TM * PIT];
    __shared__ unsigned AsL[TM * PIT];
    __shared__ unsigned BsH[TN * PIT];
    __shared__ unsigned BsL[TN * PIT];

    const int tid = threadIdx.x;
    const int m0g = blockIdx.y * TM;
    const int n0g = blockIdx.x * TN;

    const int warp = tid >> 5;
    const int lane = tid & 31;
    const int wm = warp & 1;
    const int wn = warp >> 1;
    const int g  = lane >> 2;
    const int t  = lane & 3;

    // A: row ar, half ah covers 16 k's (4 float4 from gmem)
    const int ar = tid >> 1;
    const int ah = tid & 1;
    const int am = m0g + ar;
    const float* asrc = ((am & 1) ? img : text) + (size_t)(am >> 1) * Dh + ah * 16;
    // B: row br (n), half bh covers 8 uint pairs (2 uint4 from gmem)
    const int br = tid >> 1;
    const int bh = tid & 1;
    const unsigned* bsrcH = g_BThi + (size_t)(n0g + br) * (Dh / 2) + bh * 8;
    const unsigned* bsrcL = g_BTlo + (size_t)(n0g + br) * (Dh / 2) + bh * 8;

    float acc[4][4][4];
#pragma unroll
    for (int f = 0; f < 4; f++)
#pragma unroll
        for (int j = 0; j < 4; j++)
#pragma unroll
            for (int c = 0; c < 4; c++) acc[f][j][c] = 0.0f;

    float4 aR[4];
    uint4  bRh[2], bRl[2];
#pragma unroll
    for (int q = 0; q < 4; q++) aR[q] = *(const float4*)(asrc + q * 4);
    bRh[0] = *(const uint4*)(bsrcH);     bRh[1] = *(const uint4*)(bsrcH + 4);
    bRl[0] = *(const uint4*)(bsrcL);     bRl[1] = *(const uint4*)(bsrcL + 4);

    for (int kk = 0; kk < Dh; kk += TK) {
        // ---- stage current chunk ----
        {
            float av[16];
#pragma unroll
            for (int q = 0; q < 4; q++) *(float4*)&av[q * 4] = aR[q];
            unsigned uh[8], ul[8];
#pragma unroll
            for (int p = 0; p < 8; p++) {
                __nv_bfloat162 h2 = __floats2bfloat162_rn(av[2 * p], av[2 * p + 1]);
                float hx = __bfloat162float(h2.x);
                float hy = __bfloat162float(h2.y);
                __nv_bfloat162 l2 = __floats2bfloat162_rn(av[2 * p] - hx, av[2 * p + 1] - hy);
                uh[p] = *(unsigned*)&h2;
                ul[p] = *(unsigned*)&l2;
            }
            unsigned* pH = &AsH[ar * PIT + ah * 8];
            unsigned* pL = &AsL[ar * PIT + ah * 8];
            *(uint4*)pH       = make_uint4(uh[0], uh[1], uh[2], uh[3]);
            *(uint4*)(pH + 4) = make_uint4(uh[4], uh[5], uh[6], uh[7]);
            *(uint4*)pL       = make_uint4(ul[0], ul[1], ul[2], ul[3]);
            *(uint4*)(pL + 4) = make_uint4(ul[4], ul[5], ul[6], ul[7]);

            unsigned* qH = &BsH[br * PIT + bh * 8];
            unsigned* qL = &BsL[br * PIT + bh * 8];
            *(uint4*)qH       = bRh[0];
            *(uint4*)(qH + 4) = bRh[1];
            *(uint4*)qL       = bRl[0];
            *(uint4*)(qL + 4) = bRl[1];
        }
        __syncthreads();

        // ---- prefetch next chunk ----
        if (kk + TK < Dh) {
#pragma unroll
            for (int q = 0; q < 4; q++)
                aR[q] = *(const float4*)(asrc + kk + TK + q * 4);
            const unsigned* bnH = bsrcH + (kk + TK) / 2;
            const unsigned* bnL = bsrcL + (kk + TK) / 2;
            bRh[0] = *(const uint4*)(bnH); bRh[1] = *(const uint4*)(bnH + 4);
            bRl[0] = *(const uint4*)(bnL); bRl[1] = *(const uint4*)(bnL + 4);
        }

        // ---- compute: 2 k16-steps, 3 passes each ----
#pragma unroll
        for (int ks = 0; ks < 2; ks++) {
            const int ko = ks * 8;
            unsigned aH[4][4], aL[4][4];
#pragma unroll
            for (int f = 0; f < 4; f++) {
                int r0 = (wm * 64 + f * 16 + g) * PIT + ko + t;
                int r1 = r0 + 8 * PIT;
                aH[f][0] = AsH[r0];     aH[f][1] = AsH[r1];
                aH[f][2] = AsH[r0 + 4]; aH[f][3] = AsH[r1 + 4];
                aL[f][0] = AsL[r0];     aL[f][1] = AsL[r1];
                aL[f][2] = AsL[r0 + 4]; aL[f][3] = AsL[r1 + 4];
            }
            unsigned bH[4][2], bL[4][2];
#pragma unroll
            for (int j = 0; j < 4; j++) {
                int c0i = (wn * 32 + j * 8 + g) * PIT + ko + t;
                bH[j][0] = BsH[c0i]; bH[j][1] = BsH[c0i + 4];
                bL[j][0] = BsL[c0i]; bL[j][1] = BsL[c0i + 4];
            }
#pragma unroll
            for (int f = 0; f < 4; f++)
#pragma unroll
                for (int j = 0; j < 4; j++) {
                    mma_bf16(acc[f][j][0], acc[f][j][1], acc[f][j][2], acc[f][j][3],
                             aH[f][0], aH[f][1], aH[f][2], aH[f][3], bH[j][0], bH[j][1]);
                    mma_bf16(acc[f][j][0], acc[f][j][1], acc[f][j][2], acc[f][j][3],
                             aH[f][0], aH[f][1], aH[f][2], aH[f][3], bL[j][0], bL[j][1]);
                    mma_bf16(acc[f][j][0], acc[f][j][1], acc[f][j][2], acc[f][j][3],
                             aL[f][0], aL[f][1], aL[f][2], aL[f][3], bH[j][0], bH[j][1]);
                }
        }
        __syncthreads();
    }

    // ---- epilogue (m16n8 D layout) ----
#pragma unroll
    for (int f = 0; f < 4; f++) {
        int row0 = m0g + wm * 64 + f * 16 + g;
#pragma unroll
        for (int j = 0; j < 4; j++) {
            int col = n0g + wn * 32 + j * 8 + 2 * t;
            *(float2*)&g_cw[(size_t)row0 * Dh + col] =
                make_float2(acc[f][j][0], acc[f][j][1]);
            *(float2*)&g_cw[(size_t)(row0 + 8) * Dh + col] =
                make_float2(acc[f][j][2], acc[f][j][3]);
        }
    }
}

// ---------------------------------------------------------------------------
// Kernel 2: fused co-attention — round-10 structure (measured 78us).
// One CTA/sample, 4 warps, 4 CTAs/SM. c0/c1 + accumulators in registers;
// w0/w1/wco in shared. z read ONCE per row; next row prefetched to L1.
// ---------------------------------------------------------------------------
__global__ __launch_bounds__(128, 4) void fused_coattn_kernel(
    const float* __restrict__ text,
    const float* __restrict__ img,
    const float* __restrict__ comment,
    const int*   __restrict__ comment_num,
    const float* __restrict__ W_ca,
    const float* __restrict__ b_ca,
    const float* __restrict__ W_co,
    const float* __restrict__ b_co,
    float* __restrict__ out)
{
    const int b    = blockIdx.x;
    const int tid  = threadIdx.x;
    const int lane = tid & 31;
    const int warp = tid >> 5;
    const int loff = lane * 4;

    __shared__ float sw0[Dh], sw1[Dh], swco[Dh];
    __shared__ float sbuf[4 * Dh];
    __shared__ float rA[Dh], rB[Dh], rC[Dh];
    __shared__ float swr[4];
    __shared__ float pr[8];
    __shared__ float sscal[3];

    int cn = comment_num[b];
    if (cn > Ncm) cn = Ncm;
    if (cn < 1)   cn = 1;

    const float* tp  = text + (size_t)b * Dh;
    const float* ip  = img  + (size_t)b * Dh;
    const float* w0p = g_cw + (size_t)(2 * b) * Dh;
    const float* w1p = w0p + Dh;

    for (int d = tid * 4; d < Dh; d += 128 * 4) {
        *(float4*)&sw0[d]  = *(const float4*)(w0p + d);
        *(float4*)&sw1[d]  = *(const float4*)(w1p + d);
        *(float4*)&swco[d] = *(const float4*)(W_co + d);
    }
    float c0[16], c1[16];
#pragma unroll
    for (int q = 0; q < 4; q++) {
        ((float4*)c0)[q] = *(const float4*)(tp + q * 128 + loff);
        ((float4*)c1)[q] = *(const float4*)(ip + q * 128 + loff);
    }
    __syncthreads();

    float caA[16], caB[16], accv[16];
#pragma unroll
    for (int i = 0; i < 16; i++) { caA[i] = 0.f; caB[i] = 0.f; accv[i] = 0.f; }
    float ssum = 0.0f;
    const float bco = b_co[0];

    const float* cbase = comment + (size_t)b * Ncm * Dh + loff;

    if (warp < cn) {
#pragma unroll
        for (int q = 0; q < 4; q++)
            asm volatile("prefetch.global.L1 [%0];" ::
                         "l"(cbase + (size_t)warp * Dh + q * 128));
    }
    if (warp + 4 < cn) {
#pragma unroll
        for (int q = 0; q < 4; q++)
            asm volatile("prefetch.global.L1 [%0];" ::
                         "l"(cbase + (size_t)(warp + 4) * Dh + q * 128));
    }

    for (int n = warp; n < cn; n += 4) {
        const float* crow = cbase + (size_t)n * Dh;
        float z[16];
#pragma unroll
        for (int q = 0; q < 4; q++)
            ((float4*)z)[q] = *(const float4*)(crow + q * 128);

        if (n + 8 < cn) {
            const float* prow = cbase + (size_t)(n + 8) * Dh;
#pragma unroll
            for (int q = 0; q < 4; q++)
                asm volatile("prefetch.global.L1 [%0];" :: "l"(prow + q * 128));
        }

        // co_w[k,n] = tanh(cw[k] . z[n])
        float d0 = 0.f, d1 = 0.f;
#pragma unroll
        for (int q = 0; q < 4; q++) {
            float4 a0 = *(const float4*)&sw0[q * 128 + loff];
            float4 a1 = *(const float4*)&sw1[q * 128 + loff];
            const float* zq = z + q * 4;
            d0 += a0.x * zq[0] + a0.y * zq[1] + a0.z * zq[2] + a0.w * zq[3];
            d1 += a1.x * zq[0] + a1.y * zq[1] + a1.z * zq[2] + a1.w * zq[3];
        }
#pragma unroll
        for (int o = 16; o > 0; o >>= 1) {
            d0 += __shfl_xor_sync(0xffffffffu, d0, o);
            d1 += __shfl_xor_sync(0xffffffffu, d1, o);
        }
        float co0 = fast_tanh(d0);
        float co1 = fast_tanh(d1);

        // accumulate co_w*z ; comment logit partial
        float pd = 0.f;
#pragma unroll
        for (int q = 0; q < 4; q++) {
            float4 wv = *(const float4*)&swco[q * 128 + loff];
            const float wj[4] = {wv.x, wv.y, wv.z, wv.w};
#pragma unroll
            for (int j = 0; j < 4; j++) {
                int i = q * 4 + j;
                caA[i] += co0 * z[i];
                caB[i] += co1 * z[i];
                float t = fast_tanh(z[i] + co0 * c0[i] + co1 * c1[i]);
                pd += t * wj[j];
            }
        }
#pragma unroll
        for (int o = 16; o > 0; o >>= 1)
            pd += __shfl_xor_sync(0xffffffffu, pd, o);

        // |logit| <= ||W_co||_1 ~ 18, raw exp safe in fp32.
        float e = __expf(pd + bco);
        ssum += e;
#pragma unroll
        for (int i = 0; i < 16; i++) accv[i] += e * z[i];
    }

    // ---- cross-warp reductions via smem ----
    if (lane == 0) swr[warp] = ssum;

#pragma unroll
    for (int q = 0; q < 4; q++)
        *(float4*)&sbuf[warp * Dh + q * 128 + loff] = ((float4*)caA)[q];
    __syncthreads();
    for (int d = tid; d < Dh; d += 128) {
        float s = 0.f;
#pragma unroll
        for (int w = 0; w < 4; w++) s += sbuf[w * Dh + d];
        rA[d] = s;
    }
    __syncthreads();
#pragma unroll
    for (int q = 0; q < 4; q++)
        *(float4*)&sbuf[warp * Dh + q * 128 + loff] = ((float4*)caB)[q];
    __syncthreads();
    for (int d = tid; d < Dh; d += 128) {
        float s = 0.f;
#pragma unroll
        for (int w = 0; w < 4; w++) s += sbuf[w * Dh + d];
        rB[d] = s;
    }
    __syncthreads();
#pragma unroll
    for (int q = 0; q < 4; q++)
        *(float4*)&sbuf[warp * Dh + q * 128 + loff] = ((float4*)accv)[q];
    __syncthreads();
    for (int d = tid; d < Dh; d += 128) {
        float s = 0.f;
#pragma unroll
        for (int w = 0; w < 4; w++) s += sbuf[w * Dh + d];
        rC[d] = s;
    }
    __syncthreads();

    // ---- content attention logits ----
    float p0 = 0.f, p1 = 0.f;
    for (int d = tid; d < Dh; d += 128) {
        float wa = W_ca[d];
        p0 += fast_tanh(tp[d] + rA[d]) * wa;
        p1 += fast_tanh(ip[d] + rB[d]) * wa;
    }
#pragma unroll
    for (int o = 16; o > 0; o >>= 1) {
        p0 += __shfl_xor_sync(0xffffffffu, p0, o);
        p1 += __shfl_xor_sync(0xffffffffu, p1, o);
    }
    if (lane == 0) { pr[warp] = p0; pr[4 + warp] = p1; }
    __syncthreads();

    if (tid == 0) {
        float bca = b_ca[0];
        float l0 = bca, l1 = bca;
#pragma unroll
        for (int w = 0; w < 4; w++) { l0 += pr[w]; l1 += pr[4 + w]; }
        float mx = fmaxf(l0, l1);
        float e0 = __expf(l0 - mx), e1 = __expf(l1 - mx);
        float inv = __fdividef(1.0f, e0 + e1);
        float st = 0.f;
#pragma unroll
        for (int w = 0; w < 4; w++) st += swr[w];
        sscal[0] = e0 * inv;
        sscal[1] = e1 * inv;
        sscal[2] = __fdividef(1.0f, st);
    }
    __syncthreads();

    const float cwt0 = sscal[0], cwt1 = sscal[1], invs = sscal[2];
    for (int d = tid; d < Dh; d += 128) {
        out[(size_t)b * Dh + d]         = tp[d] * cwt0 + ip[d] * cwt1;
        out[(size_t)(Bsz + b) * Dh + d] = rC[d] * invs;
    }
    if (tid == 0) {
        out[(size_t)2 * Bsz * Dh + 2 * b]     = cwt0;
        out[(size_t)2 * Bsz * Dh + 2 * b + 1] = cwt1;
    }
}

// ---------------------------------------------------------------------------
extern "C" void kernel_launch(void* const* d_in, const int* in_sizes, int n_in,
                              void* d_out, int out_size)
{
    const float* text    = (const float*)d_in[0];
    const float* img     = (const float*)d_in[1];
    const float* comment = (const float*)d_in[2];
    const int*   cnum    = (const int*)d_in[3];
    const float* cow     = (const float*)d_in[4];
    const float* W_ca    = (const float*)d_in[5];
    const float* b_ca    = (const float*)d_in[6];
    const float* W_co    = (const float*)d_in[7];
    const float* b_co    = (const float*)d_in[8];
    float* out = (float*)d_out;

    prep_bt_kernel<<<dim3(16, 16), 256>>>(cow);
    dim3 ggrid(Dh / TN, (2 * Bsz) / TM);   // (4, 32) = 128 CTAs
    gemm_cw_kernel<<<ggrid, 256>>>(text, img);
    fused_coattn_kernel<<<Bsz, 128>>>(text, img, comment, cnum,
                                      W_ca, b_ca, W_co, b_co, out);
}

// round 16
// speedup vs baseline: 1.3608x; 1.0974x over previous
#include <cuda_runtime.h>
#include <cuda_bf16.h>

#define Bsz 2048
#define Ncm 128
#define Dh  512

// 8MB scratch for cw = content @ cow  (rows interleaved: m = 2*b + k)
__device__ float g_cw[2 * Bsz * Dh];
// cow transposed + bf16-split: [e][k-pair] packed as uint ({bf(k),bf(k+1)})
__device__ unsigned g_BThi[Dh * (Dh / 2)];
__device__ unsigned g_BTlo[Dh * (Dh / 2)];

__device__ __forceinline__ float fast_tanh(float x) {
    float y;
    asm("tanh.approx.f32 %0, %1;" : "=f"(y) : "f"(x));
    return y;
}

__device__ __forceinline__ void mma_bf16(float& c0, float& c1, float& c2, float& c3,
                                         unsigned a0, unsigned a1,
                                         unsigned a2, unsigned a3,
                                         unsigned b0, unsigned b1) {
    asm("mma.sync.aligned.m16n8k16.row.col.f32.bf16.bf16.f32 "
        "{%0,%1,%2,%3}, {%4,%5,%6,%7}, {%8,%9}, {%0,%1,%2,%3};"
        : "+f"(c0), "+f"(c1), "+f"(c2), "+f"(c3)
        : "r"(a0), "r"(a1), "r"(a2), "r"(a3), "r"(b0), "r"(b1));
}

// ---------------------------------------------------------------------------
// Kernel 0: transpose + bf16-split cow -> g_BThi/g_BTlo  ([e][k/2] uint pairs)
// ---------------------------------------------------------------------------
__global__ __launch_bounds__(256) void prep_bt_kernel(const float* __restrict__ cow)
{
    __shared__ float tile[32][33];
    const int e0 = blockIdx.x * 32;
    const int d0 = blockIdx.y * 32;
    const int tx = threadIdx.x & 31;
    const int ty = threadIdx.x >> 5;      // 0..7
#pragma unroll
    for (int i = 0; i < 4; i++)
        tile[ty + 8 * i][tx] = cow[(size_t)(d0 + ty + 8 * i) * Dh + e0 + tx];
    __syncthreads();

    const int p  = threadIdx.x & 15;      // d-pair 0..15
    const int er = threadIdx.x >> 4;      // 0..15
#pragma unroll
    for (int i = 0; i < 2; i++) {
        int e = er + 16 * i;
        float x0 = tile[2 * p][e];
        float x1 = tile[2 * p + 1][e];
        __nv_bfloat162 h2 = __floats2bfloat162_rn(x0, x1);
        float hx = __bfloat162float(h2.x);
        float hy = __bfloat162float(h2.y);
        __nv_bfloat162 l2 = __floats2bfloat162_rn(x0 - hx, x1 - hy);
        size_t idx = (size_t)(e0 + e) * (Dh / 2) + (d0 >> 1) + p;
        g_BThi[idx] = *(unsigned*)&h2;
        g_BTlo[idx] = *(unsigned*)&l2;
    }
}

// ---------------------------------------------------------------------------
// Kernel 1: cw = A @ cow — bf16 tensor-core GEMM, 3-term split (unchanged).
// ---------------------------------------------------------------------------
#define TM 128
#define TN 128
#define TK 32
#define PIT 20   // uints per smem row (16 k-pairs + 4 pad)

__global__ __launch_bounds__(256) void gemm_cw_kernel(
    const float* __restrict__ text,
    const float* __restrict__ img)
{
    __shared__ unsigned AsH[TM * PIT];
    __shared__ unsigned AsL[TM * PIT];
    __shared__ unsigned BsH[TN * PIT];
    __shared__ unsigned BsL[TN * PIT];

    const int tid = threadIdx.x;
    const int m0g = blockIdx.y * TM;
    const int n0g = blockIdx.x * TN;

    const int warp = tid >> 5;
    const int lane = tid & 31;
    const int wm = warp & 1;
    const int wn = warp >> 1;
    const int g  = lane >> 2;
    const int t  = lane & 3;

    const int ar = tid >> 1;
    const int ah = tid & 1;
    const int am = m0g + ar;
    const float* asrc = ((am & 1) ? img : text) + (size_t)(am >> 1) * Dh + ah * 16;
    const int br = tid >> 1;
    const int bh = tid & 1;
    const unsigned* bsrcH = g_BThi + (size_t)(n0g + br) * (Dh / 2) + bh * 8;
    const unsigned* bsrcL = g_BTlo + (size_t)(n0g + br) * (Dh / 2) + bh * 8;

    float acc[4][4][4];
#pragma unroll
    for (int f = 0; f < 4; f++)
#pragma unroll
        for (int j = 0; j < 4; j++)
#pragma unroll
            for (int c = 0; c < 4; c++) acc[f][j][c] = 0.0f;

    float4 aR[4];
    uint4  bRh[2], bRl[2];
#pragma unroll
    for (int q = 0; q < 4; q++) aR[q] = *(const float4*)(asrc + q * 4);
    bRh[0] = *(const uint4*)(bsrcH);     bRh[1] = *(const uint4*)(bsrcH + 4);
    bRl[0] = *(const uint4*)(bsrcL);     bRl[1] = *(const uint4*)(bsrcL + 4);

    for (int kk = 0; kk < Dh; kk += TK) {
        {
            float av[16];
#pragma unroll
            for (int q = 0; q < 4; q++) *(float4*)&av[q * 4] = aR[q];
            unsigned uh[8], ul[8];
#pragma unroll
            for (int p = 0; p < 8; p++) {
                __nv_bfloat162 h2 = __floats2bfloat162_rn(av[2 * p], av[2 * p + 1]);
                float hx = __bfloat162float(h2.x);
                float hy = __bfloat162float(h2.y);
                __nv_bfloat162 l2 = __floats2bfloat162_rn(av[2 * p] - hx, av[2 * p + 1] - hy);
                uh[p] = *(unsigned*)&h2;
                ul[p] = *(unsigned*)&l2;
            }
            unsigned* pH = &AsH[ar * PIT + ah * 8];
            unsigned* pL = &AsL[ar * PIT + ah * 8];
            *(uint4*)pH       = make_uint4(uh[0], uh[1], uh[2], uh[3]);
            *(uint4*)(pH + 4) = make_uint4(uh[4], uh[5], uh[6], uh[7]);
            *(uint4*)pL       = make_uint4(ul[0], ul[1], ul[2], ul[3]);
            *(uint4*)(pL + 4) = make_uint4(ul[4], ul[5], ul[6], ul[7]);

            unsigned* qH = &BsH[br * PIT + bh * 8];
            unsigned* qL = &BsL[br * PIT + bh * 8];
            *(uint4*)qH       = bRh[0];
            *(uint4*)(qH + 4) = bRh[1];
            *(uint4*)qL       = bRl[0];
            *(uint4*)(qL + 4) = bRl[1];
        }
        __syncthreads();

        if (kk + TK < Dh) {
#pragma unroll
            for (int q = 0; q < 4; q++)
                aR[q] = *(const float4*)(asrc + kk + TK + q * 4);
            const unsigned* bnH = bsrcH + (kk + TK) / 2;
            const unsigned* bnL = bsrcL + (kk + TK) / 2;
            bRh[0] = *(const uint4*)(bnH); bRh[1] = *(const uint4*)(bnH + 4);
            bRl[0] = *(const uint4*)(bnL); bRl[1] = *(const uint4*)(bnL + 4);
        }

#pragma unroll
        for (int ks = 0; ks < 2; ks++) {
            const int ko = ks * 8;
            unsigned aH[4][4], aL[4][4];
#pragma unroll
            for (int f = 0; f < 4; f++) {
                int r0 = (wm * 64 + f * 16 + g) * PIT + ko + t;
                int r1 = r0 + 8 * PIT;
                aH[f][0] = AsH[r0];     aH[f][1] = AsH[r1];
                aH[f][2] = AsH[r0 + 4]; aH[f][3] = AsH[r1 + 4];
                aL[f][0] = AsL[r0];     aL[f][1] = AsL[r1];
                aL[f][2] = AsL[r0 + 4]; aL[f][3] = AsL[r1 + 4];
            }
            unsigned bH[4][2], bL[4][2];
#pragma unroll
            for (int j = 0; j < 4; j++) {
                int c0i = (wn * 32 + j * 8 + g) * PIT + ko + t;
                bH[j][0] = BsH[c0i]; bH[j][1] = BsH[c0i + 4];
                bL[j][0] = BsL[c0i]; bL[j][1] = BsL[c0i + 4];
            }
#pragma unroll
            for (int f = 0; f < 4; f++)
#pragma unroll
                for (int j = 0; j < 4; j++) {
                    mma_bf16(acc[f][j][0], acc[f][j][1], acc[f][j][2], acc[f][j][3],
                             aH[f][0], aH[f][1], aH[f][2], aH[f][3], bH[j][0], bH[j][1]);
                    mma_bf16(acc[f][j][0], acc[f][j][1], acc[f][j][2], acc[f][j][3],
                             aH[f][0], aH[f][1], aH[f][2], aH[f][3], bL[j][0], bL[j][1]);
                    mma_bf16(acc[f][j][0], acc[f][j][1], acc[f][j][2], acc[f][j][3],
                             aL[f][0], aL[f][1], aL[f][2], aL[f][3], bH[j][0], bH[j][1]);
                }
        }
        __syncthreads();
    }

#pragma unroll
    for (int f = 0; f < 4; f++) {
        int row0 = m0g + wm * 64 + f * 16 + g;
#pragma unroll
        for (int j = 0; j < 4; j++) {
            int col = n0g + wn * 32 + j * 8 + 2 * t;
            *(float2*)&g_cw[(size_t)row0 * Dh + col] =
                make_float2(acc[f][j][0], acc[f][j][1]);
            *(float2*)&g_cw[(size_t)(row0 + 8) * Dh + col] =
                make_float2(acc[f][j][2], acc[f][j][3]);
        }
    }
}

// ---------------------------------------------------------------------------
// Kernel 2: fused co-attention — 2-row ILP on the round-9 structure.
// One CTA/sample, 4 warps, 4 CTAs/SM. Each warp: rows (n, n+4) per iter,
// interleaved chains; butterflies batched. All big operands (w0,w1,wco,c0,c1)
// in smem; two z rows in registers. Reg target <= 128.
// ---------------------------------------------------------------------------
__global__ __launch_bounds__(128, 4) void fused_coattn_kernel(
    const float* __restrict__ text,
    const float* __restrict__ img,
    const float* __restrict__ comment,
    const int*   __restrict__ comment_num,
    const float* __restrict__ W_ca,
    const float* __restrict__ b_ca,
    const float* __restrict__ W_co,
    const float* __restrict__ b_co,
    float* __restrict__ out)
{
    const int b    = blockIdx.x;
    const int tid  = threadIdx.x;
    const int lane = tid & 31;
    const int warp = tid >> 5;
    const int loff = lane * 4;

    __shared__ float sw0[Dh], sw1[Dh], swco[Dh], sc0[Dh], sc1[Dh];  // 10 KB
    __shared__ float sbuf[4 * Dh];                                   // 8 KB
    __shared__ float rA[Dh], rB[Dh], rC[Dh];                         // 6 KB
    __shared__ float swr[4];
    __shared__ float pr[8];
    __shared__ float sscal[3];

    int cn = comment_num[b];
    if (cn > Ncm) cn = Ncm;
    if (cn < 1)   cn = 1;

    const float* tp  = text + (size_t)b * Dh;
    const float* ip  = img  + (size_t)b * Dh;
    const float* w0p = g_cw + (size_t)(2 * b) * Dh;
    const float* w1p = w0p + Dh;

    {
        int d = tid * 4;
        *(float4*)&sw0[d]  = *(const float4*)(w0p + d);
        *(float4*)&sw1[d]  = *(const float4*)(w1p + d);
        *(float4*)&swco[d] = *(const float4*)(W_co + d);
        *(float4*)&sc0[d]  = *(const float4*)(tp + d);
        *(float4*)&sc1[d]  = *(const float4*)(ip + d);
    }
    __syncthreads();

    float caA[16], caB[16], accv[16];
#pragma unroll
    for (int i = 0; i < 16; i++) { caA[i] = 0.f; caB[i] = 0.f; accv[i] = 0.f; }
    float ssum = 0.0f;
    const float bco = b_co[0];

    const float* cbase = comment + (size_t)b * Ncm * Dh + loff;

    // warm L1: first iteration's rows for this warp
#pragma unroll
    for (int r = 0; r < 2; r++) {
        int row = warp + 4 * r;
        if (row < cn) {
            const float* p = cbase + (size_t)row * Dh;
#pragma unroll
            for (int q = 0; q < 4; q++)
                asm volatile("prefetch.global.L1 [%0];" :: "l"(p + q * 128));
        }
    }

    for (int n = warp; n < cn; n += 8) {
        const int nb = n + 4;
        const bool hb = nb < cn;
        const float fb = hb ? 1.0f : 0.0f;

        float za[16], zb[16];
        {
            const float* pa = cbase + (size_t)n * Dh;
            const float* pb = cbase + (size_t)(hb ? nb : n) * Dh;
#pragma unroll
            for (int q = 0; q < 4; q++) {
                ((float4*)za)[q] = *(const float4*)(pa + q * 128);
                ((float4*)zb)[q] = *(const float4*)(pb + q * 128);
            }
        }

        // prefetch next iteration's two rows
#pragma unroll
        for (int r = 0; r < 2; r++) {
            int row = n + 8 + 4 * r;
            if (row < cn) {
                const float* p = cbase + (size_t)row * Dh;
#pragma unroll
                for (int q = 0; q < 4; q++)
                    asm volatile("prefetch.global.L1 [%0];" :: "l"(p + q * 128));
            }
        }

        // dots for both rows (operands loaded once, used twice)
        float d0a = 0.f, d1a = 0.f, d0b = 0.f, d1b = 0.f;
#pragma unroll
        for (int q = 0; q < 4; q++) {
            float4 a0 = *(const float4*)&sw0[q * 128 + loff];
            float4 a1 = *(const float4*)&sw1[q * 128 + loff];
            const float* zqa = za + q * 4;
            const float* zqb = zb + q * 4;
            d0a += a0.x * zqa[0] + a0.y * zqa[1] + a0.z * zqa[2] + a0.w * zqa[3];
            d1a += a1.x * zqa[0] + a1.y * zqa[1] + a1.z * zqa[2] + a1.w * zqa[3];
            d0b += a0.x * zqb[0] + a0.y * zqb[1] + a0.z * zqb[2] + a0.w * zqb[3];
            d1b += a1.x * zqb[0] + a1.y * zqb[1] + a1.z * zqb[2] + a1.w * zqb[3];
        }
        // batched butterfly: 4 interleaved chains
#pragma unroll
        for (int o = 16; o > 0; o >>= 1) {
            d0a += __shfl_xor_sync(0xffffffffu, d0a, o);
            d1a += __shfl_xor_sync(0xffffffffu, d1a, o);
            d0b += __shfl_xor_sync(0xffffffffu, d0b, o);
            d1b += __shfl_xor_sync(0xffffffffu, d1b, o);
        }
        float co0a = fast_tanh(d0a);
        float co1a = fast_tanh(d1a);
        float co0b = fast_tanh(d0b) * fb;
        float co1b = fast_tanh(d1b) * fb;

        // accumulate + logits, two rows interleaved
        float pda = 0.f, pdb = 0.f;
#pragma unroll
        for (int q = 0; q < 4; q++) {
            float4 wv  = *(const float4*)&swco[q * 128 + loff];
            float4 c0v = *(const float4*)&sc0[q * 128 + loff];
            float4 c1v = *(const float4*)&sc1[q * 128 + loff];
            const float wj[4] = {wv.x, wv.y, wv.z, wv.w};
            const float aj[4] = {c0v.x, c0v.y, c0v.z, c0v.w};
            const float bj[4] = {c1v.x, c1v.y, c1v.z, c1v.w};
#pragma unroll
            for (int j = 0; j < 4; j++) {
                int i = q * 4 + j;
                caA[i] += co0a * za[i] + co0b * zb[i];
                caB[i] += co1a * za[i] + co1b * zb[i];
                float ta = fast_tanh(za[i] + co0a * aj[j] + co1a * bj[j]);
                float tb = fast_tanh(zb[i] + co0b * aj[j] + co1b * bj[j]);
                pda += ta * wj[j];
                pdb += tb * wj[j];
            }
        }
#pragma unroll
        for (int o = 16; o > 0; o >>= 1) {
            pda += __shfl_xor_sync(0xffffffffu, pda, o);
            pdb += __shfl_xor_sync(0xffffffffu, pdb, o);
        }

        // |logit| <= ||W_co||_1 ~ 18, raw exp safe in fp32.
        float ea = __expf(pda + bco);
        float eb = __expf(pdb + bco) * fb;
        ssum += ea + eb;
#pragma unroll
        for (int i = 0; i < 16; i++) accv[i] += ea * za[i] + eb * zb[i];
    }

    // ---- cross-warp reductions via smem ----
    if (lane == 0) swr[warp] = ssum;

#pragma unroll
    for (int q = 0; q < 4; q++)
        *(float4*)&sbuf[warp * Dh + q * 128 + loff] = ((float4*)caA)[q];
    __syncthreads();
    for (int d = tid; d < Dh; d += 128) {
        float s = 0.f;
#pragma unroll
        for (int w = 0; w < 4; w++) s += sbuf[w * Dh + d];
        rA[d] = s;
    }
    __syncthreads();
#pragma unroll
    for (int q = 0; q < 4; q++)
        *(float4*)&sbuf[warp * Dh + q * 128 + loff] = ((float4*)caB)[q];
    __syncthreads();
    for (int d = tid; d < Dh; d += 128) {
        float s = 0.f;
#pragma unroll
        for (int w = 0; w < 4; w++) s += sbuf[w * Dh + d];
        rB[d] = s;
    }
    __syncthreads();
#pragma unroll
    for (int q = 0; q < 4; q++)
        *(float4*)&sbuf[warp * Dh + q * 128 + loff] = ((float4*)accv)[q];
    __syncthreads();
    for (int d = tid; d < Dh; d += 128) {
        float s = 0.f;
#pragma unroll
        for (int w = 0; w < 4; w++) s += sbuf[w * Dh + d];
        rC[d] = s;
    }
    __syncthreads();

    // ---- content attention logits ----
    float p0 = 0.f, p1 = 0.f;
    for (int d = tid; d < Dh; d += 128) {
        float wa = W_ca[d];
        p0 += fast_tanh(sc0[d] + rA[d]) * wa;
        p1 += fast_tanh(sc1[d] + rB[d]) * wa;
    }
#pragma unroll
    for (int o = 16; o > 0; o >>= 1) {
        p0 += __shfl_xor_sync(0xffffffffu, p0, o);
        p1 += __shfl_xor_sync(0xffffffffu, p1, o);
    }
    if (lane == 0) { pr[warp] = p0; pr[4 + warp] = p1; }
    __syncthreads();

    if (tid == 0) {
        float bca = b_ca[0];
        float l0 = bca, l1 = bca;
#pragma unroll
        for (int w = 0; w < 4; w++) { l0 += pr[w]; l1 += pr[4 + w]; }
        float mx = fmaxf(l0, l1);
        float e0 = __expf(l0 - mx), e1 = __expf(l1 - mx);
        float inv = __fdividef(1.0f, e0 + e1);
        float st = 0.f;
#pragma unroll
        for (int w = 0; w < 4; w++) st += swr[w];
        sscal[0] = e0 * inv;
        sscal[1] = e1 * inv;
        sscal[2] = __fdividef(1.0f, st);
    }
    __syncthreads();

    const float cwt0 = sscal[0], cwt1 = sscal[1], invs = sscal[2];
    for (int d = tid; d < Dh; d += 128) {
        out[(size_t)b * Dh + d]         = sc0[d] * cwt0 + sc1[d] * cwt1;
        out[(size_t)(Bsz + b) * Dh + d] = rC[d] * invs;
    }
    if (tid == 0) {
        out[(size_t)2 * Bsz * Dh + 2 * b]     = cwt0;
        out[(size_t)2 * Bsz * Dh + 2 * b + 1] = cwt1;
    }
}

// ---------------------------------------------------------------------------
extern "C" void kernel_launch(void* const* d_in, const int* in_sizes, int n_in,
                              void* d_out, int out_size)
{
    const float* text    = (const float*)d_in[0];
    const float* img     = (const float*)d_in[1];
    const float* comment = (const float*)d_in[2];
    const int*   cnum    = (const int*)d_in[3];
    const float* cow     = (const float*)d_in[4];
    const float* W_ca    = (const float*)d_in[5];
    const float* b_ca    = (const float*)d_in[6];
    const float* W_co    = (const float*)d_in[7];
    const float* b_co    = (const float*)d_in[8];
    float* out = (float*)d_out;

    prep_bt_kernel<<<dim3(16, 16), 256>>>(cow);
    dim3 ggrid(Dh / TN, (2 * Bsz) / TM);   // (4, 32) = 128 CTAs
    gemm_cw_kernel<<<ggrid, 256>>>(text, img);
    fused_coattn_kernel<<<Bsz, 128>>>(text, img, comment, cnum,
                                      W_ca, b_ca, W_co, b_co, out);
}